// round 4
// baseline (speedup 1.0000x reference)
#include <cuda_runtime.h>
#include <stdint.h>

// PatchShift: out[b,t,h,w,c] = x[b, (t - S[h%3, w%3]) % 8, h, w, c]
// Shapes: B=32, T=8, H=14, W=14, C=768 (fp32) -> rows of 192 float4.
// One CTA per (b,h,w); each thread copies its channel float4 across all T=8
// slices: 8 front-batched loads (MLP=8), then 8 stores. 32-bit indexing
// (9.63M float4 total < 2^31). Loads skip L1 (__ldcg), keep L2 (reuse seen
// across graph replays); stores default.

#define B_ 32
#define T_ 8
#define H_ 14
#define W_ 14
#define C4_ 192                         // 768 floats = 192 float4
#define TSTRIDE (H_ * W_ * C4_)         // float4 stride between time slices = 37632

__global__ __launch_bounds__(C4_) void patch_shift_kernel(
    const float4* __restrict__ x, float4* __restrict__ out)
{
    // blockIdx.x = h*14 + w (0..195), blockIdx.y = b (0..31)
    const int hw = blockIdx.x;
    const int w  = hw % 14;             // constant divisor -> mul/shift
    const int h  = hw / 14;
    const int b  = blockIdx.y;

    const int Stab[9] = {-4, 1, 2, -1, 0, 3, -2, -3, 4};
    const int s = Stab[(h % 3) * 3 + (w % 3)];

    // 32-bit base index of (b, t=0, h, w, c4=tid): max ~9.6M, fits int.
    const int base = (b * (T_ * H_ * W_) + hw) * C4_ + (int)threadIdx.x;

    float4 v[T_];
    #pragma unroll
    for (int t = 0; t < T_; ++t) {
        const int ts = (t - s + 8) & 7;          // source time slice
        v[t] = __ldcg(&x[base + ts * TSTRIDE]);
    }
    #pragma unroll
    for (int t = 0; t < T_; ++t) {
        out[base + t * TSTRIDE] = v[t];
    }
}

extern "C" void kernel_launch(void* const* d_in, const int* in_sizes, int n_in,
                              void* d_out, int out_size)
{
    const float4* x   = (const float4*)d_in[0];
    float4*       out = (float4*)d_out;

    dim3 grid(H_ * W_, B_);             // (196, 32) = 6272 CTAs, 192 thr each
    patch_shift_kernel<<<grid, C4_>>>(x, out);
}